// round 15
// baseline (speedup 1.0000x reference)
#include <cuda_runtime.h>
#include <math.h>

// Problem constants (B=8, N=180, T=256, L=16, H=64, S=240)
#define BB  8
#define NN  180
#define TT  256
#define LL  16
#define HH  64
#define SSW 240
#define K1  60
#define K2  20
#define FF  192

// ---------------- scratch ----------------------------------------------------
__device__ float d_hs[BB*NN*HH];
__device__ float d_r[BB*NN];
__device__ float d_G [BB*NN*NN];
__device__ float d_Gt[BB*NN*NN];
__device__ float d_Ne1[BB*NN*HH];
__device__ float d_row1[BB*NN];
__device__ float d_col1[BB*NN];
__device__ float d_M1[BB*NN*HH];
__device__ float d_P1[BB*NN*HH];
__device__ float d_H1[BB*NN*FF];
__device__ float d_topv1[BB*K1];
__device__ int   d_topi1[BB*K1];
__device__ float d_G1 [BB*K1*K1];
__device__ float d_Gt1[BB*K1*K1];
__device__ float d_Ne2[BB*K1*HH];
__device__ float d_row2[BB*K1];
__device__ float d_col2[BB*K1];
__device__ float d_M2[BB*K1*HH];
__device__ float d_P2[BB*K1*HH];
__device__ float d_H2[BB*K1*FF];

__device__ __forceinline__ float ex2f(float x) {
    float r; asm("ex2.approx.f32 %0, %1;" : "=f"(r) : "f"(x)); return r;
}
__device__ __forceinline__ float rcpf(float x) {
    float r; asm("rcp.approx.f32 %0, %1;" : "=f"(r) : "f"(x)); return r;
}
__device__ __forceinline__ float sigf(float x) {
    return __fdividef(1.0f, 1.0f + __expf(-x));
}
__device__ __forceinline__ unsigned f2tf32(float a) {
    unsigned r; asm("cvt.rna.tf32.f32 %0, %1;" : "=r"(r) : "f"(a)); return r;
}
__device__ __forceinline__ void mma_tf32(float* c,
    unsigned a0, unsigned a1, unsigned a2, unsigned a3,
    unsigned b0, unsigned b1) {
    asm("mma.sync.aligned.m16n8k8.row.col.f32.tf32.tf32.f32 "
        "{%0,%1,%2,%3}, {%4,%5,%6,%7}, {%8,%9}, {%0,%1,%2,%3};"
        : "+f"(c[0]), "+f"(c[1]), "+f"(c[2]), "+f"(c[3])
        : "r"(a0), "r"(a1), "r"(a2), "r"(a3), "r"(b0), "r"(b1));
}

// fused activation: sig(o)*tanh(sig(i)*tanh(g)); validated rel_err ~0
__device__ __forceinline__ float act_half(float ig, float gg, float og) {
    const float L2E = 1.4426950408889634f;
    float eI = ex2f(-L2E * ig);
    float eG = ex2f(2.0f * L2E * gg);
    float rd = rcpf((eG + 1.0f) * (eI + 1.0f));
    float c  = (eG - 1.0f) * rd;                // |c|<1
    float u  = c * c;
    float num = c * fmaf(u + 105.0f, u, 945.0f);
    float den = fmaf(fmaf(u, 15.0f, 420.0f), u, 945.0f);
    float eO = ex2f(-L2E * og);
    float rD = rcpf(den * (eO + 1.0f));
    return num * rD;
}

// ---------------- K1: lstm via tf32 MMA + ne1 (exact R10 version) -------------
__global__ void lstm_ne1_kernel(const float* __restrict__ x,
                                const float* __restrict__ W_ih,
                                const float* __restrict__ b_ih,
                                const float* __restrict__ b_hh,
                                const float* __restrict__ W1) {
    int n = blockIdx.x >> 3;
    int b = blockIdx.x & 7;
    __shared__ float sx[TT];
    __shared__ float sinv[SSW];
    __shared__ float sWf[3][16][68];
    __shared__ float sbias[3][64];
    __shared__ float swpart[8][64];
    __shared__ float sp[256];

    int tid = threadIdx.x;
    sx[tid] = x[(b * NN + n) * TT + tid];
    const float* Wn = W_ih + n * 256 * LL;
#pragma unroll
    for (int gate = 0; gate < 3; gate++) {
        int base = (gate == 0) ? 0 : (gate == 1 ? 128 : 192);
        for (int idx = tid; idx < 64 * 16; idx += 256) {
            int j = idx >> 4, l = idx & 15;
            sWf[gate][l][j] = Wn[(base + j) * LL + l];
        }
        if (tid < 64)
            sbias[gate][tid] = b_ih[n * 256 + base + tid] + b_hh[n * 256 + base + tid];
    }
    __syncthreads();
    if (tid < SSW) sinv[tid] = __fdividef(1.0f, sx[LL + tid]);
    __syncthreads();

    int warp = tid >> 5, lane = tid & 31;
    int g = lane >> 2, t = lane & 3;

    for (int nt = 0; nt < 8; nt++) {
        unsigned Bh[3][2][2], Bl[3][2][2];
#pragma unroll
        for (int gate = 0; gate < 3; gate++)
#pragma unroll
            for (int ki = 0; ki < 2; ki++) {
                float w0 = sWf[gate][ki * 8 + t][nt * 8 + g];
                float w1 = sWf[gate][ki * 8 + t + 4][nt * 8 + g];
                unsigned h0 = f2tf32(w0), h1 = f2tf32(w1);
                Bh[gate][ki][0] = h0;
                Bh[gate][ki][1] = h1;
                Bl[gate][ki][0] = f2tf32(w0 - __uint_as_float(h0));
                Bl[gate][ki][1] = f2tf32(w1 - __uint_as_float(h1));
            }

        float cs0 = 0.0f, cs1 = 0.0f;
        for (int mt = warp; mt < 15; mt += 8) {
            int s0 = mt * 16;
            float C0[4] = {0, 0, 0, 0}, C1[4] = {0, 0, 0, 0}, C2[4] = {0, 0, 0, 0};
#pragma unroll
            for (int ki = 0; ki < 2; ki++) {
                int k0 = ki * 8;
                float a0f = sx[s0 + g + k0 + t];
                float a1f = sx[s0 + 8 + g + k0 + t];
                float a2f = sx[s0 + g + k0 + t + 4];
                float a3f = sx[s0 + 8 + g + k0 + t + 4];
                unsigned ah0 = f2tf32(a0f), ah1 = f2tf32(a1f);
                unsigned ah2 = f2tf32(a2f), ah3 = f2tf32(a3f);
                unsigned al0 = f2tf32(a0f - __uint_as_float(ah0));
                unsigned al1 = f2tf32(a1f - __uint_as_float(ah1));
                unsigned al2 = f2tf32(a2f - __uint_as_float(ah2));
                unsigned al3 = f2tf32(a3f - __uint_as_float(ah3));
                mma_tf32(C0, ah0, ah1, ah2, ah3, Bh[0][ki][0], Bh[0][ki][1]);
                mma_tf32(C0, al0, al1, al2, al3, Bh[0][ki][0], Bh[0][ki][1]);
                mma_tf32(C0, ah0, ah1, ah2, ah3, Bl[0][ki][0], Bl[0][ki][1]);
                mma_tf32(C1, ah0, ah1, ah2, ah3, Bh[1][ki][0], Bh[1][ki][1]);
                mma_tf32(C1, al0, al1, al2, al3, Bh[1][ki][0], Bh[1][ki][1]);
                mma_tf32(C1, ah0, ah1, ah2, ah3, Bl[1][ki][0], Bl[1][ki][1]);
                mma_tf32(C2, ah0, ah1, ah2, ah3, Bh[2][ki][0], Bh[2][ki][1]);
                mma_tf32(C2, al0, al1, al2, al3, Bh[2][ki][0], Bh[2][ki][1]);
                mma_tf32(C2, ah0, ah1, ah2, ah3, Bl[2][ki][0], Bl[2][ki][1]);
            }
            int j0 = nt * 8 + 2 * t;
            float bI0 = sbias[0][j0], bI1 = sbias[0][j0 + 1];
            float bG0 = sbias[1][j0], bG1 = sbias[1][j0 + 1];
            float bO0 = sbias[2][j0], bO1 = sbias[2][j0 + 1];
            float iv0 = sinv[s0 + g], iv1 = sinv[s0 + 8 + g];
            cs0 = fmaf(act_half(C0[0] + bI0, C1[0] + bG0, C2[0] + bO0), iv0, cs0);
            cs1 = fmaf(act_half(C0[1] + bI1, C1[1] + bG1, C2[1] + bO1), iv0, cs1);
            cs0 = fmaf(act_half(C0[2] + bI0, C1[2] + bG0, C2[2] + bO0), iv1, cs0);
            cs1 = fmaf(act_half(C0[3] + bI1, C1[3] + bG1, C2[3] + bO1), iv1, cs1);
        }
        cs0 += __shfl_down_sync(0xffffffffu, cs0, 16);
        cs1 += __shfl_down_sync(0xffffffffu, cs1, 16);
        cs0 += __shfl_down_sync(0xffffffffu, cs0, 8);
        cs1 += __shfl_down_sync(0xffffffffu, cs1, 8);
        cs0 += __shfl_down_sync(0xffffffffu, cs0, 4);
        cs1 += __shfl_down_sync(0xffffffffu, cs1, 4);
        if (lane < 4) {
            swpart[warp][nt * 8 + 2 * t]     = cs0;
            swpart[warp][nt * 8 + 2 * t + 1] = cs1;
        }
    }
    __syncthreads();
    if (tid < HH) {
        float s = 0.0f;
#pragma unroll
        for (int w = 0; w < 8; w++) s += swpart[w][tid];
        d_hs[(b * NN + n) * HH + tid] = s;
    }
    // r = sum(sinv) deterministic tree
    sp[tid] = (tid < SSW) ? sinv[tid] : 0.0f;
    __syncthreads();
    if (tid < 128) sp[tid] += sp[tid + 128];
    __syncthreads();
    if (tid < 64) sp[tid] += sp[tid + 64];
    __syncthreads();
    if (tid < 32) {
        float v = sp[tid] + sp[tid + 32];
#pragma unroll
        for (int off = 16; off > 0; off >>= 1)
            v += __shfl_down_sync(0xffffffffu, v, off);
        if (tid == 0) d_r[b * NN + n] = v;
    }
    __syncthreads();
    // Ne1 row
    {
        int o = tid & 63, g4 = tid >> 6;
        float a = 0.0f;
        for (int k = g4 * 64; k < g4 * 64 + 64; k++)
            a = fmaf(sx[k], W1[k * HH + o], a);
        sp[tid] = a;
        __syncthreads();
        if (tid < HH)
            d_Ne1[(b * NN + n) * HH + tid] = sp[tid] + sp[tid + 64] + sp[tid + 128] + sp[tid + 192];
    }
}

// ---------------- K2: gmat — coalesced d_Gt only, 384 thr (b-split 2) ---------
__global__ __launch_bounds__(384) void gmat_kernel(const float* __restrict__ W_fc,
                                                   const float* __restrict__ b_fc) {
    int n = blockIdx.x;
    __shared__ float sh[BB * HH];
    __shared__ float srr[BB];
    int tid = threadIdx.x;   // 384
    for (int t = tid; t < BB * HH; t += 384) {
        int b = t >> 6;
        sh[t] = d_hs[(b * NN + n) * HH + (t & 63)];
    }
    if (tid < BB) srr[tid] = d_r[tid * NN + n];
    __syncthreads();
    int j = tid % 192;
    int half = tid / 192;      // 0 or 1 -> batches [0..3] or [4..7]
    if (j < NN) {
        const float4* w = (const float4*)(W_fc + (n * NN + j) * HH);
        float bfc = b_fc[n * NN + j];
        int b0 = half * 4;
        float acc[4];
#pragma unroll
        for (int bb = 0; bb < 4; bb++) acc[bb] = bfc * srr[b0 + bb];
#pragma unroll
        for (int h4 = 0; h4 < HH / 4; h4++) {
            float4 wv = w[h4];
#pragma unroll
            for (int bb = 0; bb < 4; bb++) {
                const float* shb = sh + (b0 + bb) * HH + h4 * 4;
                acc[bb] = fmaf(wv.x, shb[0], acc[bb]);
                acc[bb] = fmaf(wv.y, shb[1], acc[bb]);
                acc[bb] = fmaf(wv.z, shb[2], acc[bb]);
                acc[bb] = fmaf(wv.w, shb[3], acc[bb]);
            }
        }
#pragma unroll
        for (int bb = 0; bb < 4; bb++)
            d_Gt[((b0 + bb) * NN + n) * NN + j] = acc[bb] * (1.0f / (float)SSW);
    }
}

// ---------------- K3: transpose d_G[b,j,n] = d_Gt[b,n,j] ----------------------
__global__ void gtrans_kernel() {
    __shared__ float tile[32][33];
    int b  = blockIdx.z;
    int n0 = blockIdx.x * 32;
    int j0 = blockIdx.y * 32;
    int tx = threadIdx.x, ty = threadIdx.y;   // 32 x 8
    for (int r = ty; r < 32; r += 8) {
        int nn = n0 + r, jj = j0 + tx;
        if (nn < NN && jj < NN)
            tile[r][tx] = d_Gt[(b * NN + nn) * NN + jj];
    }
    __syncthreads();
    for (int r = ty; r < 32; r += 8) {
        int jj = j0 + r, nn = n0 + tx;
        if (jj < NN && nn < NN)
            d_G[(b * NN + jj) * NN + nn] = tile[tx][r];
    }
}

// ---------------- mp1: 2 rows/block, 256 thr (R10-measured) -------------------
__global__ void mp1_kernel() {
    const int Nn = NN;
    __shared__ float sG [2][NN];
    __shared__ float sGt[2][NN];
    __shared__ float red[4][2][HH];
    int nt = Nn / 2;
    int b  = blockIdx.x / nt;
    int it = (blockIdx.x - b * nt) * 2;
    int tid = threadIdx.x;
    int o = tid & 63, q = tid >> 6;
    const int chunk = Nn / 4;
    for (int idx = tid; idx < 2 * Nn; idx += 256) {
        int ii = idx / Nn, k = idx - ii * Nn;
        sG [ii][k] = d_G [(b * Nn + it + ii) * Nn + k];
        sGt[ii][k] = d_Gt[(b * Nn + it + ii) * Nn + k];
    }
    __syncthreads();
    {
        int w = tid >> 5, lane = tid & 31;
        if (w < 4) {
            int ii = w & 1, kind = w >> 1;
            float t = 0.0f;
            const float (*tile)[NN] = kind ? sGt : sG;
            for (int k = lane; k < Nn; k += 32) t += tile[ii][k];
#pragma unroll
            for (int off = 16; off > 0; off >>= 1)
                t += __shfl_down_sync(0xffffffffu, t, off);
            if (lane == 0) {
                if (kind == 0) d_row1[b * Nn + it + ii] = t;
                else           d_col1[b * Nn + it + ii] = t;
            }
        }
    }
    float m[2] = {0, 0}, p[2] = {0, 0};
    for (int k = q * chunk; k < (q + 1) * chunk; k++) {
        float ne = d_Ne1[(b * Nn + k) * HH + o];
#pragma unroll
        for (int ii = 0; ii < 2; ii++) {
            m[ii] = fmaf(sG [ii][k], ne, m[ii]);
            p[ii] = fmaf(sGt[ii][k], ne, p[ii]);
        }
    }
#pragma unroll
    for (int ii = 0; ii < 2; ii++) red[q][ii][o] = m[ii];
    __syncthreads();
    if (q < 2)
        d_M1[(b * Nn + it + q) * HH + o] = red[0][q][o] + red[1][q][o] + red[2][q][o] + red[3][q][o];
    __syncthreads();
#pragma unroll
    for (int ii = 0; ii < 2; ii++) red[q][ii][o] = p[ii];
    __syncthreads();
    if (q < 2)
        d_P1[(b * Nn + it + q) * HH + o] = red[0][q][o] + red[1][q][o] + red[2][q][o] + red[3][q][o];
}

// ---------------- hcat1: 2 rows/block, 256 thr (R10-measured) -----------------
__global__ void hcat1_kernel() {
    const int Nn = NN;
    __shared__ float sG [2][NN];
    __shared__ float sGt[2][NN];
    __shared__ float sir[NN];
    __shared__ float sic[NN];
    __shared__ float red[4][2][HH];
    int nt = Nn / 2;
    int b  = blockIdx.x / nt;
    int it = (blockIdx.x - b * nt) * 2;
    int tid = threadIdx.x;
    int o = tid & 63, q = tid >> 6;
    const int chunk = Nn / 4;
    for (int k = tid; k < Nn; k += 256) {
        sir[k] = __fdividef(1.0f, d_row1[b * Nn + k]);
        sic[k] = __fdividef(1.0f, d_col1[b * Nn + k]);
    }
    for (int idx = tid; idx < 2 * Nn; idx += 256) {
        int ii = idx / Nn, k = idx - ii * Nn;
        sG [ii][k] = d_G [(b * Nn + it + ii) * Nn + k];
        sGt[ii][k] = d_Gt[(b * Nn + it + ii) * Nn + k];
    }
    __syncthreads();
    float a2[2] = {0, 0}, a3[2] = {0, 0};
    for (int k = q * chunk; k < (q + 1) * chunk; k++) {
        float mv = d_M1[(b * Nn + k) * HH + o] * sir[k];
        float pv = d_P1[(b * Nn + k) * HH + o] * sic[k];
#pragma unroll
        for (int ii = 0; ii < 2; ii++) {
            a2[ii] = fmaf(sGt[ii][k], mv, a2[ii]);
            a3[ii] = fmaf(sG [ii][k], pv, a3[ii]);
        }
    }
#pragma unroll
    for (int ii = 0; ii < 2; ii++) red[q][ii][o] = a2[ii];
    __syncthreads();
    if (q < 2)
        d_H1[(b * Nn + it + q) * FF + HH + o] =
            fmaxf(0.0f, red[0][q][o] + red[1][q][o] + red[2][q][o] + red[3][q][o]);
    __syncthreads();
#pragma unroll
    for (int ii = 0; ii < 2; ii++) red[q][ii][o] = a3[ii];
    __syncthreads();
    if (q < 2) {
        d_H1[(b * Nn + it + q) * FF + 2 * HH + o] =
            fmaxf(0.0f, red[0][q][o] + red[1][q][o] + red[2][q][o] + red[3][q][o]);
        int i = it + q;
        float m0 = d_M1[(b * Nn + i) * HH + o];
        float p0 = d_P1[(b * Nn + i) * HH + o];
        d_H1[(b * Nn + i) * FF + o] = fmaxf(0.0f, 0.5f * (m0 + p0));
    }
}

// ---------------- topk1 (8 blocks, 256 thr) -----------------------------------
__global__ void topk1_kernel(const float* __restrict__ w) {
    __shared__ float ss[NN];
    __shared__ float sw[FF];
    __shared__ float rtmp[256];
    __shared__ float srn_s;
    int b = blockIdx.x, tid = threadIdx.x;
    rtmp[tid] = 0.0f;
    if (tid < FF) { float v = w[tid]; sw[tid] = v; rtmp[tid] = v * v; }
    __syncthreads();
    for (int st = 128; st > 32; st >>= 1) {
        if (tid < st) rtmp[tid] += rtmp[tid + st];
        __syncthreads();
    }
    if (tid < 32) {
        float v = rtmp[tid] + rtmp[tid + 32];
#pragma unroll
        for (int off = 16; off > 0; off >>= 1)
            v += __shfl_down_sync(0xffffffffu, v, off);
        if (tid == 0) srn_s = rsqrtf(v);
    }
    __syncthreads();
    float srn = srn_s;
    int wrp = tid >> 5, lane = tid & 31;
    for (int n = wrp; n < NN; n += 8) {
        const float* hp = d_H1 + (b * NN + n) * FF;
        float acc = 0.0f;
        for (int f = lane; f < FF; f += 32) acc = fmaf(hp[f], sw[f], acc);
#pragma unroll
        for (int off = 16; off > 0; off >>= 1)
            acc += __shfl_down_sync(0xffffffffu, acc, off);
        if (lane == 0) ss[n] = acc * srn;
    }
    __syncthreads();
    if (tid < NN) {
        float v = ss[tid];
        int cnt = 0;
        for (int m = 0; m < NN; m++) {
            float u = ss[m];
            cnt += (u > v) || ((u == v) && (m < tid));
        }
        if (cnt < K1) { d_topi1[b * K1 + cnt] = tid; d_topv1[b * K1 + cnt] = v; }
    }
}

// ---------------- gather (G1, Gt1) + Ne2 (480 blocks, 192 thr) ----------------
__global__ void gather_ne2_kernel(const float* __restrict__ W2) {
    __shared__ int   sti[K1];
    __shared__ float shg[FF];
    __shared__ float red[3][HH];
    int b = blockIdx.x / K1;
    int rr = blockIdx.x - b * K1;
    int tid = threadIdx.x;   // 192
    if (tid < K1) sti[tid] = d_topi1[b * K1 + tid];
    int src = d_topi1[b * K1 + rr];
    float gate = sigf(d_topv1[b * K1 + rr]);
    shg[tid] = d_H1[(b * NN + src) * FF + tid] * gate;
    __syncthreads();
    if (tid < K1) {
        d_G1 [(b * K1 + rr) * K1 + tid] = d_G [(b * NN + src) * NN + sti[tid]];
        d_Gt1[(b * K1 + rr) * K1 + tid] = d_Gt[(b * NN + src) * NN + sti[tid]];
    }
    int o = tid & 63, g = tid >> 6;
    float acc = 0.0f;
    for (int f = g * 64; f < (g + 1) * 64; f++)
        acc = fmaf(shg[f], W2[f * HH + o], acc);
    red[g][o] = acc;
    __syncthreads();
    if (tid < HH)
        d_Ne2[(b * K1 + rr) * HH + tid] = red[0][tid] + red[1][tid] + red[2][tid];
}

// ---------------- mp2: 4 rows/block, 120 blocks -------------------------------
__global__ void mp2_kernel() {
    const int Nn = K1;
    __shared__ float sG [4][K1];
    __shared__ float sGt[4][K1];
    __shared__ float red[4][4][HH];
    int nt = Nn / 4;
    int b  = blockIdx.x / nt;
    int it = (blockIdx.x - b * nt) * 4;
    int tid = threadIdx.x;
    int o = tid & 63, q = tid >> 6;
    const int chunk = Nn / 4;
    for (int idx = tid; idx < 4 * Nn; idx += 256) {
        int ii = idx / Nn, k = idx - ii * Nn;
        sG [ii][k] = d_G1 [(b * Nn + it + ii) * Nn + k];
        sGt[ii][k] = d_Gt1[(b * Nn + it + ii) * Nn + k];
    }
    __syncthreads();
    {
        int w = tid >> 5, lane = tid & 31;
        int ii = w & 3, kind = w >> 2;
        float t = 0.0f;
        const float (*tile)[K1] = kind ? sGt : sG;
        for (int k = lane; k < Nn; k += 32) t += tile[ii][k];
#pragma unroll
        for (int off = 16; off > 0; off >>= 1)
            t += __shfl_down_sync(0xffffffffu, t, off);
        if (lane == 0) {
            if (kind == 0) d_row2[b * Nn + it + ii] = t;
            else           d_col2[b * Nn + it + ii] = t;
        }
    }
    float m[4] = {0, 0, 0, 0}, p[4] = {0, 0, 0, 0};
    for (int k = q * chunk; k < (q + 1) * chunk; k++) {
        float ne = d_Ne2[(b * Nn + k) * HH + o];
#pragma unroll
        for (int ii = 0; ii < 4; ii++) {
            m[ii] = fmaf(sG [ii][k], ne, m[ii]);
            p[ii] = fmaf(sGt[ii][k], ne, p[ii]);
        }
    }
#pragma unroll
    for (int ii = 0; ii < 4; ii++) red[q][ii][o] = m[ii];
    __syncthreads();
    d_M2[(b * Nn + it + q) * HH + o] = red[0][q][o] + red[1][q][o] + red[2][q][o] + red[3][q][o];
    __syncthreads();
#pragma unroll
    for (int ii = 0; ii < 4; ii++) red[q][ii][o] = p[ii];
    __syncthreads();
    d_P2[(b * Nn + it + q) * HH + o] = red[0][q][o] + red[1][q][o] + red[2][q][o] + red[3][q][o];
}

// ---------------- hcat2: 4 rows/block, 120 blocks -----------------------------
__global__ void hcat2_kernel() {
    const int Nn = K1;
    __shared__ float sG [4][K1];
    __shared__ float sGt[4][K1];
    __shared__ float sir[K1];
    __shared__ float sic[K1];
    __shared__ float red[4][4][HH];
    int nt = Nn / 4;
    int b  = blockIdx.x / nt;
    int it = (blockIdx.x - b * nt) * 4;
    int tid = threadIdx.x;
    int o = tid & 63, q = tid >> 6;
    const int chunk = Nn / 4;
    for (int k = tid; k < Nn; k += 256) {
        sir[k] = __fdividef(1.0f, d_row2[b * Nn + k]);
        sic[k] = __fdividef(1.0f, d_col2[b * Nn + k]);
    }
    for (int idx = tid; idx < 4 * Nn; idx += 256) {
        int ii = idx / Nn, k = idx - ii * Nn;
        sG [ii][k] = d_G1 [(b * Nn + it + ii) * Nn + k];
        sGt[ii][k] = d_Gt1[(b * Nn + it + ii) * Nn + k];
    }
    __syncthreads();
    float a2[4] = {0, 0, 0, 0}, a3[4] = {0, 0, 0, 0};
    for (int k = q * chunk; k < (q + 1) * chunk; k++) {
        float mv = d_M2[(b * Nn + k) * HH + o] * sir[k];
        float pv = d_P2[(b * Nn + k) * HH + o] * sic[k];
#pragma unroll
        for (int ii = 0; ii < 4; ii++) {
            a2[ii] = fmaf(sGt[ii][k], mv, a2[ii]);
            a3[ii] = fmaf(sG [ii][k], pv, a3[ii]);
        }
    }
#pragma unroll
    for (int ii = 0; ii < 4; ii++) red[q][ii][o] = a2[ii];
    __syncthreads();
    d_H2[(b * Nn + it + q) * FF + HH + o] =
        fmaxf(0.0f, red[0][q][o] + red[1][q][o] + red[2][q][o] + red[3][q][o]);
    __syncthreads();
#pragma unroll
    for (int ii = 0; ii < 4; ii++) red[q][ii][o] = a3[ii];
    __syncthreads();
    {
        d_H2[(b * Nn + it + q) * FF + 2 * HH + o] =
            fmaxf(0.0f, red[0][q][o] + red[1][q][o] + red[2][q][o] + red[3][q][o]);
        int i = it + q;
        float m0 = d_M2[(b * Nn + i) * HH + o];
        float p0 = d_P2[(b * Nn + i) * HH + o];
        d_H2[(b * Nn + i) * FF + o] = fmaxf(0.0f, 0.5f * (m0 + p0));
    }
}

// ---------------- topk2 + final (8 blocks, 256 thr) ---------------------------
__global__ void topk2_final_kernel(const float* __restrict__ w,
                                   const float* __restrict__ W_out,
                                   const float* __restrict__ b_out,
                                   float* __restrict__ out) {
    __shared__ float ss[K1];
    __shared__ float sw[FF];
    __shared__ float rtmp[256];
    __shared__ float s1buf[256];
    __shared__ float srn_s;
    __shared__ int   sti2[K2];
    __shared__ float sgate[K2];
    int b = blockIdx.x, tid = threadIdx.x;
    rtmp[tid] = 0.0f;
    if (tid < FF) { float v = w[tid]; sw[tid] = v; rtmp[tid] = v * v; }
    __syncthreads();
    for (int st = 128; st > 32; st >>= 1) {
        if (tid < st) rtmp[tid] += rtmp[tid + st];
        __syncthreads();
    }
    if (tid < 32) {
        float v = rtmp[tid] + rtmp[tid + 32];
#pragma unroll
        for (int off = 16; off > 0; off >>= 1)
            v += __shfl_down_sync(0xffffffffu, v, off);
        if (tid == 0) srn_s = rsqrtf(v);
    }
    __syncthreads();
    float srn = srn_s;
    int wrp = tid >> 5, lane = tid & 31;
    for (int n = wrp; n < K1; n += 8) {
        const float* hp = d_H2 + (b * K1 + n) * FF;
        float acc = 0.0f;
        for (int f = lane; f < FF; f += 32) acc = fmaf(hp[f], sw[f], acc);
#pragma unroll
        for (int off = 16; off > 0; off >>= 1)
            acc += __shfl_down_sync(0xffffffffu, acc, off);
        if (lane == 0) ss[n] = acc * srn;
    }
    __syncthreads();
    if (tid < K1) {
        float v = ss[tid];
        int cnt = 0;
        for (int m = 0; m < K1; m++) {
            float u = ss[m];
            cnt += (u > v) || ((u == v) && (m < tid));
        }
        if (cnt < K2) { sti2[cnt] = tid; sgate[cnt] = sigf(v); }
    }
    __syncthreads();

    float a0 = 0.0f, a1 = 0.0f;
    const float2* Wo = (const float2*)W_out;
    for (int f = tid; f < K2 * FF; f += 256) {
        int rr = f / FF, ff = f - rr * FF;
        float hv = d_H2[(b * K1 + sti2[rr]) * FF + ff] * sgate[rr];
        float2 wv = Wo[f];
        a0 = fmaf(hv, wv.x, a0);
        a1 = fmaf(hv, wv.y, a1);
    }
    rtmp[tid] = a0; s1buf[tid] = a1;
    __syncthreads();
    for (int st = 128; st > 0; st >>= 1) {
        if (tid < st) { rtmp[tid] += rtmp[tid + st]; s1buf[tid] += s1buf[tid + st]; }
        __syncthreads();
    }
    if (tid == 0) {
        float l0 = rtmp[0] + b_out[0];
        float l1 = s1buf[0] + b_out[1];
        float m = fmaxf(l0, l1);
        float e0 = expf(l0 - m), e1 = expf(l1 - m);
        float inv = 1.0f / (e0 + e1);
        out[b * 2 + 0] = e0 * inv;
        out[b * 2 + 1] = e1 * inv;
    }
}

// ---------------- launch -----------------------------------------------------
extern "C" void kernel_launch(void* const* d_in, const int* in_sizes, int n_in,
                              void* d_out, int out_size) {
    (void)in_sizes; (void)n_in; (void)out_size;
    const float* x     = (const float*)d_in[0];
    const float* W_ih  = (const float*)d_in[1];
    const float* b_ih  = (const float*)d_in[2];
    const float* b_hh  = (const float*)d_in[3];
    const float* W_fc  = (const float*)d_in[4];
    const float* b_fc  = (const float*)d_in[5];
    const float* W1    = (const float*)d_in[6];
    const float* W2    = (const float*)d_in[7];
    const float* w1    = (const float*)d_in[8];
    const float* w2    = (const float*)d_in[9];
    const float* W_out = (const float*)d_in[10];
    const float* b_out = (const float*)d_in[11];
    float* out = (float*)d_out;

    lstm_ne1_kernel<<<BB * NN, 256>>>(x, W_ih, b_ih, b_hh, W1);
    gmat_kernel<<<NN, 384>>>(W_fc, b_fc);
    {
        dim3 g(6, 6, 8), t(32, 8);
        gtrans_kernel<<<g, t>>>();
    }
    mp1_kernel<<<BB * (NN / 2), 256>>>();
    hcat1_kernel<<<BB * (NN / 2), 256>>>();
    topk1_kernel<<<BB, 256>>>(w1);
    gather_ne2_kernel<<<BB * K1, 192>>>(W2);
    mp2_kernel<<<BB * (K1 / 4), 256>>>();
    hcat2_kernel<<<BB * (K1 / 4), 256>>>();
    topk2_final_kernel<<<BB, 256>>>(w2, W_out, b_out, out);
}

// round 16
// speedup vs baseline: 1.0839x; 1.0839x over previous
#include <cuda_runtime.h>
#include <math.h>

// Problem constants (B=8, N=180, T=256, L=16, H=64, S=240)
#define BB  8
#define NN  180
#define TT  256
#define LL  16
#define HH  64
#define SSW 240
#define K1  60
#define K2  20
#define FF  192

// ---------------- scratch ----------------------------------------------------
__device__ float d_hs[BB*NN*HH];
__device__ float d_r[BB*NN];
__device__ float d_G [BB*NN*NN];
__device__ float d_Gt[BB*NN*NN];
__device__ float d_Ne1[BB*NN*HH];
__device__ float d_row1[BB*NN];
__device__ float d_col1[BB*NN];
__device__ float d_M1[BB*NN*HH];
__device__ float d_P1[BB*NN*HH];
__device__ float d_H1[BB*NN*FF];
__device__ float d_topv1[BB*K1];
__device__ int   d_topi1[BB*K1];
__device__ float d_G1 [BB*K1*K1];
__device__ float d_Gt1[BB*K1*K1];
__device__ float d_Ne2[BB*K1*HH];
__device__ float d_row2[BB*K1];
__device__ float d_col2[BB*K1];
__device__ float d_M2[BB*K1*HH];
__device__ float d_P2[BB*K1*HH];
__device__ float d_H2[BB*K1*FF];

__device__ __forceinline__ float ex2f(float x) {
    float r; asm("ex2.approx.f32 %0, %1;" : "=f"(r) : "f"(x)); return r;
}
__device__ __forceinline__ float rcpf(float x) {
    float r; asm("rcp.approx.f32 %0, %1;" : "=f"(r) : "f"(x)); return r;
}
__device__ __forceinline__ float sigf(float x) {
    return __fdividef(1.0f, 1.0f + __expf(-x));
}
__device__ __forceinline__ unsigned f2tf32(float a) {
    unsigned r; asm("cvt.rna.tf32.f32 %0, %1;" : "=r"(r) : "f"(a)); return r;
}
__device__ __forceinline__ void mma_tf32(float* c,
    unsigned a0, unsigned a1, unsigned a2, unsigned a3,
    unsigned b0, unsigned b1) {
    asm("mma.sync.aligned.m16n8k8.row.col.f32.tf32.tf32.f32 "
        "{%0,%1,%2,%3}, {%4,%5,%6,%7}, {%8,%9}, {%0,%1,%2,%3};"
        : "+f"(c[0]), "+f"(c[1]), "+f"(c[2]), "+f"(c[3])
        : "r"(a0), "r"(a1), "r"(a2), "r"(a3), "r"(b0), "r"(b1));
}

// fused activation: sig(o)*tanh(sig(i)*tanh(g)); validated rel_err ~0
__device__ __forceinline__ float act_half(float ig, float gg, float og) {
    const float L2E = 1.4426950408889634f;
    float eI = ex2f(-L2E * ig);
    float eG = ex2f(2.0f * L2E * gg);
    float rd = rcpf((eG + 1.0f) * (eI + 1.0f));
    float c  = (eG - 1.0f) * rd;                // |c|<1
    float u  = c * c;
    float num = c * fmaf(u + 105.0f, u, 945.0f);
    float den = fmaf(fmaf(u, 15.0f, 420.0f), u, 945.0f);
    float eO = ex2f(-L2E * og);
    float rD = rcpf(den * (eO + 1.0f));
    return num * rD;
}

// ---------------- K1: lstm via tf32 MMA + ne1; splits precomputed in smem -----
__global__ void lstm_ne1_kernel(const float* __restrict__ x,
                                const float* __restrict__ W_ih,
                                const float* __restrict__ b_ih,
                                const float* __restrict__ b_hh,
                                const float* __restrict__ W1) {
    int n = blockIdx.x >> 3;
    int b = blockIdx.x & 7;
    __shared__ float    sx[TT];
    __shared__ unsigned sxh[TT];
    __shared__ unsigned sxl[TT];
    __shared__ float    sinv[SSW];
    __shared__ unsigned sWh[3][16][68];
    __shared__ unsigned sWl[3][16][68];
    __shared__ float    sbias[3][64];
    __shared__ float    swpart[8][64];
    __shared__ float    sp[256];

    int tid = threadIdx.x;
    {
        float v = x[(b * NN + n) * TT + tid];
        unsigned h = f2tf32(v);
        sx[tid]  = v;
        sxh[tid] = h;
        sxl[tid] = f2tf32(v - __uint_as_float(h));
    }
    const float* Wn = W_ih + n * 256 * LL;
#pragma unroll
    for (int gate = 0; gate < 3; gate++) {
        int base = (gate == 0) ? 0 : (gate == 1 ? 128 : 192);
        for (int idx = tid; idx < 64 * 16; idx += 256) {
            int j = idx >> 4, l = idx & 15;
            float w = Wn[(base + j) * LL + l];
            unsigned h = f2tf32(w);
            sWh[gate][l][j] = h;
            sWl[gate][l][j] = f2tf32(w - __uint_as_float(h));
        }
        if (tid < 64)
            sbias[gate][tid] = b_ih[n * 256 + base + tid] + b_hh[n * 256 + base + tid];
    }
    __syncthreads();
    if (tid < SSW) sinv[tid] = __fdividef(1.0f, sx[LL + tid]);
    __syncthreads();

    int warp = tid >> 5, lane = tid & 31;
    int g = lane >> 2, t = lane & 3;

    for (int nt = 0; nt < 8; nt++) {
        unsigned Bh[3][2][2], Bl[3][2][2];
#pragma unroll
        for (int gate = 0; gate < 3; gate++)
#pragma unroll
            for (int ki = 0; ki < 2; ki++) {
                Bh[gate][ki][0] = sWh[gate][ki * 8 + t][nt * 8 + g];
                Bh[gate][ki][1] = sWh[gate][ki * 8 + t + 4][nt * 8 + g];
                Bl[gate][ki][0] = sWl[gate][ki * 8 + t][nt * 8 + g];
                Bl[gate][ki][1] = sWl[gate][ki * 8 + t + 4][nt * 8 + g];
            }

        float cs0 = 0.0f, cs1 = 0.0f;
        for (int mt = warp; mt < 15; mt += 8) {
            int s0 = mt * 16;
            float C0[4] = {0, 0, 0, 0}, C1[4] = {0, 0, 0, 0}, C2[4] = {0, 0, 0, 0};
#pragma unroll
            for (int ki = 0; ki < 2; ki++) {
                int k0 = ki * 8;
                unsigned ah0 = sxh[s0 + g + k0 + t];
                unsigned ah1 = sxh[s0 + 8 + g + k0 + t];
                unsigned ah2 = sxh[s0 + g + k0 + t + 4];
                unsigned ah3 = sxh[s0 + 8 + g + k0 + t + 4];
                unsigned al0 = sxl[s0 + g + k0 + t];
                unsigned al1 = sxl[s0 + 8 + g + k0 + t];
                unsigned al2 = sxl[s0 + g + k0 + t + 4];
                unsigned al3 = sxl[s0 + 8 + g + k0 + t + 4];
                mma_tf32(C0, ah0, ah1, ah2, ah3, Bh[0][ki][0], Bh[0][ki][1]);
                mma_tf32(C0, al0, al1, al2, al3, Bh[0][ki][0], Bh[0][ki][1]);
                mma_tf32(C0, ah0, ah1, ah2, ah3, Bl[0][ki][0], Bl[0][ki][1]);
                mma_tf32(C1, ah0, ah1, ah2, ah3, Bh[1][ki][0], Bh[1][ki][1]);
                mma_tf32(C1, al0, al1, al2, al3, Bh[1][ki][0], Bh[1][ki][1]);
                mma_tf32(C1, ah0, ah1, ah2, ah3, Bl[1][ki][0], Bl[1][ki][1]);
                mma_tf32(C2, ah0, ah1, ah2, ah3, Bh[2][ki][0], Bh[2][ki][1]);
                mma_tf32(C2, al0, al1, al2, al3, Bh[2][ki][0], Bh[2][ki][1]);
                mma_tf32(C2, ah0, ah1, ah2, ah3, Bl[2][ki][0], Bl[2][ki][1]);
            }
            int j0 = nt * 8 + 2 * t;
            float bI0 = sbias[0][j0], bI1 = sbias[0][j0 + 1];
            float bG0 = sbias[1][j0], bG1 = sbias[1][j0 + 1];
            float bO0 = sbias[2][j0], bO1 = sbias[2][j0 + 1];
            float iv0 = sinv[s0 + g], iv1 = sinv[s0 + 8 + g];
            cs0 = fmaf(act_half(C0[0] + bI0, C1[0] + bG0, C2[0] + bO0), iv0, cs0);
            cs1 = fmaf(act_half(C0[1] + bI1, C1[1] + bG1, C2[1] + bO1), iv0, cs1);
            cs0 = fmaf(act_half(C0[2] + bI0, C1[2] + bG0, C2[2] + bO0), iv1, cs0);
            cs1 = fmaf(act_half(C0[3] + bI1, C1[3] + bG1, C2[3] + bO1), iv1, cs1);
        }
        cs0 += __shfl_down_sync(0xffffffffu, cs0, 16);
        cs1 += __shfl_down_sync(0xffffffffu, cs1, 16);
        cs0 += __shfl_down_sync(0xffffffffu, cs0, 8);
        cs1 += __shfl_down_sync(0xffffffffu, cs1, 8);
        cs0 += __shfl_down_sync(0xffffffffu, cs0, 4);
        cs1 += __shfl_down_sync(0xffffffffu, cs1, 4);
        if (lane < 4) {
            swpart[warp][nt * 8 + 2 * t]     = cs0;
            swpart[warp][nt * 8 + 2 * t + 1] = cs1;
        }
    }
    __syncthreads();
    if (tid < HH) {
        float s = 0.0f;
#pragma unroll
        for (int w = 0; w < 8; w++) s += swpart[w][tid];
        d_hs[(b * NN + n) * HH + tid] = s;
    }
    // r = sum(sinv) deterministic tree
    sp[tid] = (tid < SSW) ? sinv[tid] : 0.0f;
    __syncthreads();
    if (tid < 128) sp[tid] += sp[tid + 128];
    __syncthreads();
    if (tid < 64) sp[tid] += sp[tid + 64];
    __syncthreads();
    if (tid < 32) {
        float v = sp[tid] + sp[tid + 32];
#pragma unroll
        for (int off = 16; off > 0; off >>= 1)
            v += __shfl_down_sync(0xffffffffu, v, off);
        if (tid == 0) d_r[b * NN + n] = v;
    }
    __syncthreads();
    // Ne1 row
    {
        int o = tid & 63, g4 = tid >> 6;
        float a = 0.0f;
        for (int k = g4 * 64; k < g4 * 64 + 64; k++)
            a = fmaf(sx[k], W1[k * HH + o], a);
        sp[tid] = a;
        __syncthreads();
        if (tid < HH)
            d_Ne1[(b * NN + n) * HH + tid] = sp[tid] + sp[tid + 64] + sp[tid + 128] + sp[tid + 192];
    }
}

// ---------------- K2: G + Gt (R10 version) ------------------------------------
__global__ void gmat_kernel(const float* __restrict__ W_fc,
                            const float* __restrict__ b_fc) {
    int n = blockIdx.x;
    __shared__ float sh[BB * HH];
    __shared__ float srr[BB];
    int tid = threadIdx.x;   // 192
    for (int t = tid; t < BB * HH; t += 192) {
        int b = t >> 6;
        sh[t] = d_hs[(b * NN + n) * HH + (t & 63)];
    }
    if (tid < BB) srr[tid] = d_r[tid * NN + n];
    __syncthreads();
    if (tid < NN) {
        int j = tid;
        const float4* w = (const float4*)(W_fc + (n * NN + j) * HH);
        float bfc = b_fc[n * NN + j];
        float acc[BB];
#pragma unroll
        for (int b = 0; b < BB; b++) acc[b] = bfc * srr[b];
#pragma unroll
        for (int h4 = 0; h4 < HH / 4; h4++) {
            float4 wv = w[h4];
#pragma unroll
            for (int b = 0; b < BB; b++) {
                const float* shb = sh + b * HH + h4 * 4;
                acc[b] = fmaf(wv.x, shb[0], acc[b]);
                acc[b] = fmaf(wv.y, shb[1], acc[b]);
                acc[b] = fmaf(wv.z, shb[2], acc[b]);
                acc[b] = fmaf(wv.w, shb[3], acc[b]);
            }
        }
#pragma unroll
        for (int b = 0; b < BB; b++) {
            float g = acc[b] * (1.0f / (float)SSW);
            d_G [(b * NN + j) * NN + n] = g;
            d_Gt[(b * NN + n) * NN + j] = g;
        }
    }
}

// ---------------- mp1: 2 rows/block, 256 thr (R10) ----------------------------
__global__ void mp1_kernel() {
    const int Nn = NN;
    __shared__ float sG [2][NN];
    __shared__ float sGt[2][NN];
    __shared__ float red[4][2][HH];
    int nt = Nn / 2;
    int b  = blockIdx.x / nt;
    int it = (blockIdx.x - b * nt) * 2;
    int tid = threadIdx.x;
    int o = tid & 63, q = tid >> 6;
    const int chunk = Nn / 4;
    for (int idx = tid; idx < 2 * Nn; idx += 256) {
        int ii = idx / Nn, k = idx - ii * Nn;
        sG [ii][k] = d_G [(b * Nn + it + ii) * Nn + k];
        sGt[ii][k] = d_Gt[(b * Nn + it + ii) * Nn + k];
    }
    __syncthreads();
    {
        int w = tid >> 5, lane = tid & 31;
        if (w < 4) {
            int ii = w & 1, kind = w >> 1;
            float t = 0.0f;
            const float (*tile)[NN] = kind ? sGt : sG;
            for (int k = lane; k < Nn; k += 32) t += tile[ii][k];
#pragma unroll
            for (int off = 16; off > 0; off >>= 1)
                t += __shfl_down_sync(0xffffffffu, t, off);
            if (lane == 0) {
                if (kind == 0) d_row1[b * Nn + it + ii] = t;
                else           d_col1[b * Nn + it + ii] = t;
            }
        }
    }
    float m[2] = {0, 0}, p[2] = {0, 0};
    for (int k = q * chunk; k < (q + 1) * chunk; k++) {
        float ne = d_Ne1[(b * Nn + k) * HH + o];
#pragma unroll
        for (int ii = 0; ii < 2; ii++) {
            m[ii] = fmaf(sG [ii][k], ne, m[ii]);
            p[ii] = fmaf(sGt[ii][k], ne, p[ii]);
        }
    }
#pragma unroll
    for (int ii = 0; ii < 2; ii++) red[q][ii][o] = m[ii];
    __syncthreads();
    if (q < 2)
        d_M1[(b * Nn + it + q) * HH + o] = red[0][q][o] + red[1][q][o] + red[2][q][o] + red[3][q][o];
    __syncthreads();
#pragma unroll
    for (int ii = 0; ii < 2; ii++) red[q][ii][o] = p[ii];
    __syncthreads();
    if (q < 2)
        d_P1[(b * Nn + it + q) * HH + o] = red[0][q][o] + red[1][q][o] + red[2][q][o] + red[3][q][o];
}

// ---------------- hcat1: 2 rows/block, 256 thr (R10) --------------------------
__global__ void hcat1_kernel() {
    const int Nn = NN;
    __shared__ float sG [2][NN];
    __shared__ float sGt[2][NN];
    __shared__ float sir[NN];
    __shared__ float sic[NN];
    __shared__ float red[4][2][HH];
    int nt = Nn / 2;
    int b  = blockIdx.x / nt;
    int it = (blockIdx.x - b * nt) * 2;
    int tid = threadIdx.x;
    int o = tid & 63, q = tid >> 6;
    const int chunk = Nn / 4;
    for (int k = tid; k < Nn; k += 256) {
        sir[k] = __fdividef(1.0f, d_row1[b * Nn + k]);
        sic[k] = __fdividef(1.0f, d_col1[b * Nn + k]);
    }
    for (int idx = tid; idx < 2 * Nn; idx += 256) {
        int ii = idx / Nn, k = idx - ii * Nn;
        sG [ii][k] = d_G [(b * Nn + it + ii) * Nn + k];
        sGt[ii][k] = d_Gt[(b * Nn + it + ii) * Nn + k];
    }
    __syncthreads();
    float a2[2] = {0, 0}, a3[2] = {0, 0};
    for (int k = q * chunk; k < (q + 1) * chunk; k++) {
        float mv = d_M1[(b * Nn + k) * HH + o] * sir[k];
        float pv = d_P1[(b * Nn + k) * HH + o] * sic[k];
#pragma unroll
        for (int ii = 0; ii < 2; ii++) {
            a2[ii] = fmaf(sGt[ii][k], mv, a2[ii]);
            a3[ii] = fmaf(sG [ii][k], pv, a3[ii]);
        }
    }
#pragma unroll
    for (int ii = 0; ii < 2; ii++) red[q][ii][o] = a2[ii];
    __syncthreads();
    if (q < 2)
        d_H1[(b * Nn + it + q) * FF + HH + o] =
            fmaxf(0.0f, red[0][q][o] + red[1][q][o] + red[2][q][o] + red[3][q][o]);
    __syncthreads();
#pragma unroll
    for (int ii = 0; ii < 2; ii++) red[q][ii][o] = a3[ii];
    __syncthreads();
    if (q < 2) {
        d_H1[(b * Nn + it + q) * FF + 2 * HH + o] =
            fmaxf(0.0f, red[0][q][o] + red[1][q][o] + red[2][q][o] + red[3][q][o]);
        int i = it + q;
        float m0 = d_M1[(b * Nn + i) * HH + o];
        float p0 = d_P1[(b * Nn + i) * HH + o];
        d_H1[(b * Nn + i) * FF + o] = fmaxf(0.0f, 0.5f * (m0 + p0));
    }
}

// ---------------- topk1 (8 blocks, 256 thr) -----------------------------------
__global__ void topk1_kernel(const float* __restrict__ w) {
    __shared__ float ss[NN];
    __shared__ float sw[FF];
    __shared__ float rtmp[256];
    __shared__ float srn_s;
    int b = blockIdx.x, tid = threadIdx.x;
    rtmp[tid] = 0.0f;
    if (tid < FF) { float v = w[tid]; sw[tid] = v; rtmp[tid] = v * v; }
    __syncthreads();
    for (int st = 128; st > 32; st >>= 1) {
        if (tid < st) rtmp[tid] += rtmp[tid + st];
        __syncthreads();
    }
    if (tid < 32) {
        float v = rtmp[tid] + rtmp[tid + 32];
#pragma unroll
        for (int off = 16; off > 0; off >>= 1)
            v += __shfl_down_sync(0xffffffffu, v, off);
        if (tid == 0) srn_s = rsqrtf(v);
    }
    __syncthreads();
    float srn = srn_s;
    int wrp = tid >> 5, lane = tid & 31;
    for (int n = wrp; n < NN; n += 8) {
        const float* hp = d_H1 + (b * NN + n) * FF;
        float acc = 0.0f;
        for (int f = lane; f < FF; f += 32) acc = fmaf(hp[f], sw[f], acc);
#pragma unroll
        for (int off = 16; off > 0; off >>= 1)
            acc += __shfl_down_sync(0xffffffffu, acc, off);
        if (lane == 0) ss[n] = acc * srn;
    }
    __syncthreads();
    if (tid < NN) {
        float v = ss[tid];
        int cnt = 0;
        for (int m = 0; m < NN; m++) {
            float u = ss[m];
            cnt += (u > v) || ((u == v) && (m < tid));
        }
        if (cnt < K1) { d_topi1[b * K1 + cnt] = tid; d_topv1[b * K1 + cnt] = v; }
    }
}

// ---------------- gather (G1, Gt1) + Ne2 (480 blocks, 192 thr) ----------------
__global__ void gather_ne2_kernel(const float* __restrict__ W2) {
    __shared__ int   sti[K1];
    __shared__ float shg[FF];
    __shared__ float red[3][HH];
    int b = blockIdx.x / K1;
    int rr = blockIdx.x - b * K1;
    int tid = threadIdx.x;   // 192
    if (tid < K1) sti[tid] = d_topi1[b * K1 + tid];
    int src = d_topi1[b * K1 + rr];
    float gate = sigf(d_topv1[b * K1 + rr]);
    shg[tid] = d_H1[(b * NN + src) * FF + tid] * gate;
    __syncthreads();
    if (tid < K1) {
        d_G1 [(b * K1 + rr) * K1 + tid] = d_G [(b * NN + src) * NN + sti[tid]];
        d_Gt1[(b * K1 + rr) * K1 + tid] = d_Gt[(b * NN + src) * NN + sti[tid]];
    }
    int o = tid & 63, g = tid >> 6;
    float acc = 0.0f;
    for (int f = g * 64; f < (g + 1) * 64; f++)
        acc = fmaf(shg[f], W2[f * HH + o], acc);
    red[g][o] = acc;
    __syncthreads();
    if (tid < HH)
        d_Ne2[(b * K1 + rr) * HH + tid] = red[0][tid] + red[1][tid] + red[2][tid];
}

// ---------------- mp2: 4 rows/block, 120 blocks -------------------------------
__global__ void mp2_kernel() {
    const int Nn = K1;
    __shared__ float sG [4][K1];
    __shared__ float sGt[4][K1];
    __shared__ float red[4][4][HH];
    int nt = Nn / 4;
    int b  = blockIdx.x / nt;
    int it = (blockIdx.x - b * nt) * 4;
    int tid = threadIdx.x;
    int o = tid & 63, q = tid >> 6;
    const int chunk = Nn / 4;
    for (int idx = tid; idx < 4 * Nn; idx += 256) {
        int ii = idx / Nn, k = idx - ii * Nn;
        sG [ii][k] = d_G1 [(b * Nn + it + ii) * Nn + k];
        sGt[ii][k] = d_Gt1[(b * Nn + it + ii) * Nn + k];
    }
    __syncthreads();
    {
        int w = tid >> 5, lane = tid & 31;
        int ii = w & 3, kind = w >> 2;
        float t = 0.0f;
        const float (*tile)[K1] = kind ? sGt : sG;
        for (int k = lane; k < Nn; k += 32) t += tile[ii][k];
#pragma unroll
        for (int off = 16; off > 0; off >>= 1)
            t += __shfl_down_sync(0xffffffffu, t, off);
        if (lane == 0) {
            if (kind == 0) d_row2[b * Nn + it + ii] = t;
            else           d_col2[b * Nn + it + ii] = t;
        }
    }
    float m[4] = {0, 0, 0, 0}, p[4] = {0, 0, 0, 0};
    for (int k = q * chunk; k < (q + 1) * chunk; k++) {
        float ne = d_Ne2[(b * Nn + k) * HH + o];
#pragma unroll
        for (int ii = 0; ii < 4; ii++) {
            m[ii] = fmaf(sG [ii][k], ne, m[ii]);
            p[ii] = fmaf(sGt[ii][k], ne, p[ii]);
        }
    }
#pragma unroll
    for (int ii = 0; ii < 4; ii++) red[q][ii][o] = m[ii];
    __syncthreads();
    d_M2[(b * Nn + it + q) * HH + o] = red[0][q][o] + red[1][q][o] + red[2][q][o] + red[3][q][o];
    __syncthreads();
#pragma unroll
    for (int ii = 0; ii < 4; ii++) red[q][ii][o] = p[ii];
    __syncthreads();
    d_P2[(b * Nn + it + q) * HH + o] = red[0][q][o] + red[1][q][o] + red[2][q][o] + red[3][q][o];
}

// ---------------- hcat2: 4 rows/block, 120 blocks -----------------------------
__global__ void hcat2_kernel() {
    const int Nn = K1;
    __shared__ float sG [4][K1];
    __shared__ float sGt[4][K1];
    __shared__ float sir[K1];
    __shared__ float sic[K1];
    __shared__ float red[4][4][HH];
    int nt = Nn / 4;
    int b  = blockIdx.x / nt;
    int it = (blockIdx.x - b * nt) * 4;
    int tid = threadIdx.x;
    int o = tid & 63, q = tid >> 6;
    const int chunk = Nn / 4;
    for (int k = tid; k < Nn; k += 256) {
        sir[k] = __fdividef(1.0f, d_row2[b * Nn + k]);
        sic[k] = __fdividef(1.0f, d_col2[b * Nn + k]);
    }
    for (int idx = tid; idx < 4 * Nn; idx += 256) {
        int ii = idx / Nn, k = idx - ii * Nn;
        sG [ii][k] = d_G1 [(b * Nn + it + ii) * Nn + k];
        sGt[ii][k] = d_Gt1[(b * Nn + it + ii) * Nn + k];
    }
    __syncthreads();
    float a2[4] = {0, 0, 0, 0}, a3[4] = {0, 0, 0, 0};
    for (int k = q * chunk; k < (q + 1) * chunk; k++) {
        float mv = d_M2[(b * Nn + k) * HH + o] * sir[k];
        float pv = d_P2[(b * Nn + k) * HH + o] * sic[k];
#pragma unroll
        for (int ii = 0; ii < 4; ii++) {
            a2[ii] = fmaf(sGt[ii][k], mv, a2[ii]);
            a3[ii] = fmaf(sG [ii][k], pv, a3[ii]);
        }
    }
#pragma unroll
    for (int ii = 0; ii < 4; ii++) red[q][ii][o] = a2[ii];
    __syncthreads();
    d_H2[(b * Nn + it + q) * FF + HH + o] =
        fmaxf(0.0f, red[0][q][o] + red[1][q][o] + red[2][q][o] + red[3][q][o]);
    __syncthreads();
#pragma unroll
    for (int ii = 0; ii < 4; ii++) red[q][ii][o] = a3[ii];
    __syncthreads();
    {
        d_H2[(b * Nn + it + q) * FF + 2 * HH + o] =
            fmaxf(0.0f, red[0][q][o] + red[1][q][o] + red[2][q][o] + red[3][q][o]);
        int i = it + q;
        float m0 = d_M2[(b * Nn + i) * HH + o];
        float p0 = d_P2[(b * Nn + i) * HH + o];
        d_H2[(b * Nn + i) * FF + o] = fmaxf(0.0f, 0.5f * (m0 + p0));
    }
}

// ---------------- topk2 + final (8 blocks, 256 thr) ---------------------------
__global__ void topk2_final_kernel(const float* __restrict__ w,
                                   const float* __restrict__ W_out,
                                   const float* __restrict__ b_out,
                                   float* __restrict__ out) {
    __shared__ float ss[K1];
    __shared__ float sw[FF];
    __shared__ float rtmp[256];
    __shared__ float s1buf[256];
    __shared__ float srn_s;
    __shared__ int   sti2[K2];
    __shared__ float sgate[K2];
    int b = blockIdx.x, tid = threadIdx.x;
    rtmp[tid] = 0.0f;
    if (tid < FF) { float v = w[tid]; sw[tid] = v; rtmp[tid] = v * v; }
    __syncthreads();
    for (int st = 128; st > 32; st >>= 1) {
        if (tid < st) rtmp[tid] += rtmp[tid + st];
        __syncthreads();
    }
    if (tid < 32) {
        float v = rtmp[tid] + rtmp[tid + 32];
#pragma unroll
        for (int off = 16; off > 0; off >>= 1)
            v += __shfl_down_sync(0xffffffffu, v, off);
        if (tid == 0) srn_s = rsqrtf(v);
    }
    __syncthreads();
    float srn = srn_s;
    int wrp = tid >> 5, lane = tid & 31;
    for (int n = wrp; n < K1; n += 8) {
        const float* hp = d_H2 + (b * K1 + n) * FF;
        float acc = 0.0f;
        for (int f = lane; f < FF; f += 32) acc = fmaf(hp[f], sw[f], acc);
#pragma unroll
        for (int off = 16; off > 0; off >>= 1)
            acc += __shfl_down_sync(0xffffffffu, acc, off);
        if (lane == 0) ss[n] = acc * srn;
    }
    __syncthreads();
    if (tid < K1) {
        float v = ss[tid];
        int cnt = 0;
        for (int m = 0; m < K1; m++) {
            float u = ss[m];
            cnt += (u > v) || ((u == v) && (m < tid));
        }
        if (cnt < K2) { sti2[cnt] = tid; sgate[cnt] = sigf(v); }
    }
    __syncthreads();

    float a0 = 0.0f, a1 = 0.0f;
    const float2* Wo = (const float2*)W_out;
    for (int f = tid; f < K2 * FF; f += 256) {
        int rr = f / FF, ff = f - rr * FF;
        float hv = d_H2[(b * K1 + sti2[rr]) * FF + ff] * sgate[rr];
        float2 wv = Wo[f];
        a0 = fmaf(hv, wv.x, a0);
        a1 = fmaf(hv, wv.y, a1);
    }
    rtmp[tid] = a0; s1buf[tid] = a1;
    __syncthreads();
    for (int st = 128; st > 0; st >>= 1) {
        if (tid < st) { rtmp[tid] += rtmp[tid + st]; s1buf[tid] += s1buf[tid + st]; }
        __syncthreads();
    }
    if (tid == 0) {
        float l0 = rtmp[0] + b_out[0];
        float l1 = s1buf[0] + b_out[1];
        float m = fmaxf(l0, l1);
        float e0 = expf(l0 - m), e1 = expf(l1 - m);
        float inv = 1.0f / (e0 + e1);
        out[b * 2 + 0] = e0 * inv;
        out[b * 2 + 1] = e1 * inv;
    }
}

// ---------------- launch -----------------------------------------------------
extern "C" void kernel_launch(void* const* d_in, const int* in_sizes, int n_in,
                              void* d_out, int out_size) {
    (void)in_sizes; (void)n_in; (void)out_size;
    const float* x     = (const float*)d_in[0];
    const float* W_ih  = (const float*)d_in[1];
    const float* b_ih  = (const float*)d_in[2];
    const float* b_hh  = (const float*)d_in[3];
    const float* W_fc  = (const float*)d_in[4];
    const float* b_fc  = (const float*)d_in[5];
    const float* W1    = (const float*)d_in[6];
    const float* W2    = (const float*)d_in[7];
    const float* w1    = (const float*)d_in[8];
    const float* w2    = (const float*)d_in[9];
    const float* W_out = (const float*)d_in[10];
    const float* b_out = (const float*)d_in[11];
    float* out = (float*)d_out;

    lstm_ne1_kernel<<<BB * NN, 256>>>(x, W_ih, b_ih, b_hh, W1);
    gmat_kernel<<<NN, 192>>>(W_fc, b_fc);
    mp1_kernel<<<BB * (NN / 2), 256>>>();
    hcat1_kernel<<<BB * (NN / 2), 256>>>();
    topk1_kernel<<<BB, 256>>>(w1);
    gather_ne2_kernel<<<BB * K1, 192>>>(W2);
    mp2_kernel<<<BB * (K1 / 4), 256>>>();
    hcat2_kernel<<<BB * (K1 / 4), 256>>>();
    topk2_final_kernel<<<BB, 256>>>(w2, W_out, b_out, out);
}